// round 1
// baseline (speedup 1.0000x reference)
#include <cuda_runtime.h>

#define NAG    12
#define HIDD   64
#define NENV   4096
#define NNODE  (NENV*NAG)
#define TPB    384

// shared memory float offsets
#define OFF_WA   0        // 128x64 = 8192  (We1 node-part / Wh1)
#define OFF_WB   8192     // 64x64  = 4096  (W_embed / We2 / Wh2)
#define OFF_H    12288    // 12x64  = 768
#define OFF_P    13056    // 12x128 = 1536  (P1|P2, reused as t1)
#define OFF_AGG  14592    // 12x64  = 768
#define OFF_XS   15360    // 12x12  = 144
#define OFF_RAD  15504    // 132x4  = 528
#define OFF_MS   16032    // 12x4x64= 3072  (per-warp m1 scratch)
#define SMEM_FLOATS 19104
#define SMEM_BYTES  (SMEM_FLOATS*4)

__device__ __forceinline__ float siluf(float v) {
    return v / (1.0f + __expf(-v));
}

extern "C" __global__ void __launch_bounds__(TPB, 2)
egnn_kernel(const float* __restrict__ h0,   const float* __restrict__ x0,
            const float* __restrict__ Wemb, const float* __restrict__ bemb,
            const float* __restrict__ We1,  const float* __restrict__ be1,
            const float* __restrict__ We2,  const float* __restrict__ be2,
            const float* __restrict__ Wx,   const float* __restrict__ bx,
            const float* __restrict__ Wh1,  const float* __restrict__ bh1,
            const float* __restrict__ Wh2,  const float* __restrict__ bh2,
            const float* __restrict__ w_act,const float* __restrict__ log_std,
            float* __restrict__ out)
{
    extern __shared__ float sm[];
    float* WA  = sm + OFF_WA;
    float* WB  = sm + OFF_WB;
    float* hs  = sm + OFF_H;
    float* P   = sm + OFF_P;
    float* agg = sm + OFF_AGG;
    float* xs  = sm + OFF_XS;
    float* rad = sm + OFF_RAD;
    float* ms  = sm + OFF_MS;

    const int tid  = threadIdx.x;
    const int w    = tid >> 5;
    const int lane = tid & 31;
    const int env  = blockIdx.x;
    const int base = env * NAG;

    // ---------- phase 0: stage x, W_embed; embed h ----------
    if (tid < NAG * NAG) xs[tid] = x0[base * 12 + tid];
    {
        float4* q = (float4*)WB;
        const float4* g = (const float4*)Wemb;
        for (int i = tid; i < 512; i += TPB) q[i] = g[i];
    }
    __syncthreads();
    {   // warp w -> node w : h = h0 @ Wemb + bemb
        const int n = w;
        float a0 = __ldg(&bemb[lane]);
        float a1 = __ldg(&bemb[lane + 32]);
        const float* h0p = h0 + (base + n) * 32;
        #pragma unroll
        for (int k = 0; k < 32; k++) {
            float hk = __ldg(&h0p[k]);
            a0 += hk * WB[k * 64 + lane];
            a1 += hk * WB[k * 64 + lane + 32];
        }
        hs[n * 64 + lane] = a0;
        hs[n * 64 + lane + 32] = a1;
    }

    // ---------- layers ----------
    for (int l = 0; l < 2; l++) {
        __syncthreads();
        // load WA <- We1[l] rows 0..127, WB <- We2[l]
        {
            float4* q = (float4*)WA;
            const float4* g = (const float4*)We1 + l * 2112;   // 8448/4
            for (int i = tid; i < 2048; i += TPB) q[i] = g[i];
            float4* q2 = (float4*)WB;
            const float4* g2 = (const float4*)We2 + l * 1024;
            for (int i = tid; i < 1024; i += TPB) q2[i] = g2[i];
        }
        // radial per edge (132 edges, threads 0..131)
        if (tid < 132) {
            int e = tid, i = e / 11, tt = e - 11 * i, j = tt + (tt >= i);
            float s0 = 0.f, s1 = 0.f, s2 = 0.f, s3 = 0.f;
            #pragma unroll
            for (int d = 0; d < 3; d++) {
                float d0 = xs[i*12 + d*4 + 0] - xs[j*12 + d*4 + 0]; s0 += d0*d0;
                float d1 = xs[i*12 + d*4 + 1] - xs[j*12 + d*4 + 1]; s1 += d1*d1;
                float d2 = xs[i*12 + d*4 + 2] - xs[j*12 + d*4 + 2]; s2 += d2*d2;
                float d3 = xs[i*12 + d*4 + 3] - xs[j*12 + d*4 + 3]; s3 += d3*d3;
            }
            ((float4*)rad)[e] = make_float4(s0, s1, s2, s3);
        }
        __syncthreads();
        // P-phase: P[n][0:64]=h@We1[0:64]+be1, P[n][64:128]=h@We1[64:128]
        {
            const int n = w;
            float a0 = __ldg(&be1[l*64 + lane]);
            float a1 = __ldg(&be1[l*64 + lane + 32]);
            float a2 = 0.f, a3 = 0.f;
            #pragma unroll
            for (int k = 0; k < 64; k++) {
                float hk = hs[n*64 + k];
                a0 += hk * WA[k*64 + lane];
                a1 += hk * WA[k*64 + lane + 32];
                a2 += hk * WA[(64+k)*64 + lane];
                a3 += hk * WA[(64+k)*64 + lane + 32];
            }
            P[n*128 + lane]      = a0;
            P[n*128 + lane + 32] = a1;
            P[n*128 + 64 + lane] = a2;
            P[n*128 + 96 + lane] = a3;
        }
        __syncthreads();
        // ---------- edge phase: warp w owns node i=w (its 11 in-edges) ----------
        {
            const int i = w;
            const float4 wxA = __ldg((const float4*)&Wx[l*256 + lane*4]);
            const float4 wxB = __ldg((const float4*)&Wx[l*256 + (lane+32)*4]);
            const float4 bxv = __ldg((const float4*)&bx[l*4]);
            const float be2a = __ldg(&be2[l*64 + lane]);
            const float be2b = __ldg(&be2[l*64 + lane + 32]);
            float wrA[4], wrB[4];
            #pragma unroll
            for (int v = 0; v < 4; v++) {
                wrA[v] = __ldg(&We1[l*8448 + (128+v)*64 + lane]);
                wrB[v] = __ldg(&We1[l*8448 + (128+v)*64 + lane + 32]);
            }
            const float Pi0  = P[i*128 + lane];
            const float Pi32 = P[i*128 + 32 + lane];
            const float xi   = (lane < 12) ? xs[i*12 + lane] : 0.f;
            float aggA = 0.f, aggB = 0.f, dxr = 0.f;
            float* msw = ms + w * 256;

            for (int g0 = 0; g0 < 11; g0 += 4) {
                const int cnt = (11 - g0 < 4) ? (11 - g0) : 4;
                // MLP1: m1 = silu(P1[i] + P2[j] + radial@Wr)
                #pragma unroll
                for (int gg = 0; gg < 4; gg++) if (gg < cnt) {
                    int tt = g0 + gg, j = tt + (tt >= i);
                    float4 rv = ((const float4*)rad)[i*11 + tt];
                    float aA = Pi0  + P[j*128 + 64 + lane]
                             + rv.x*wrA[0] + rv.y*wrA[1] + rv.z*wrA[2] + rv.w*wrA[3];
                    float aB = Pi32 + P[j*128 + 96 + lane]
                             + rv.x*wrB[0] + rv.y*wrB[1] + rv.z*wrB[2] + rv.w*wrB[3];
                    msw[gg*64 + lane]      = siluf(aA);
                    msw[gg*64 + lane + 32] = siluf(aB);
                }
                __syncwarp();
                // MLP2: m = silu(m1 @ We2 + be2) — weights amortized over 4 edges
                float acc0[4] = {be2a, be2a, be2a, be2a};
                float acc1[4] = {be2b, be2b, be2b, be2b};
                #pragma unroll
                for (int k4 = 0; k4 < 16; k4++) {
                    float w00 = WB[(4*k4+0)*64 + lane];
                    float w01 = WB[(4*k4+1)*64 + lane];
                    float w02 = WB[(4*k4+2)*64 + lane];
                    float w03 = WB[(4*k4+3)*64 + lane];
                    float w10 = WB[(4*k4+0)*64 + lane + 32];
                    float w11 = WB[(4*k4+1)*64 + lane + 32];
                    float w12 = WB[(4*k4+2)*64 + lane + 32];
                    float w13 = WB[(4*k4+3)*64 + lane + 32];
                    #pragma unroll
                    for (int gg = 0; gg < 4; gg++) if (gg < cnt) {
                        float4 aq = *((const float4*)&msw[gg*64 + k4*4]);
                        acc0[gg] += aq.x*w00 + aq.y*w01 + aq.z*w02 + aq.w*w03;
                        acc1[gg] += aq.x*w10 + aq.y*w11 + aq.z*w12 + aq.w*w13;
                    }
                }
                // epilogue: agg accumulate + wc reduce + dx accumulate
                #pragma unroll
                for (int gg = 0; gg < 4; gg++) if (gg < cnt) {
                    float m0  = siluf(acc0[gg]);
                    float m1v = siluf(acc1[gg]);
                    aggA += m0; aggB += m1v;
                    float p0 = m0*wxA.x + m1v*wxB.x;
                    float p1 = m0*wxA.y + m1v*wxB.y;
                    float p2 = m0*wxA.z + m1v*wxB.z;
                    float p3 = m0*wxA.w + m1v*wxB.w;
                    #pragma unroll
                    for (int off = 16; off; off >>= 1) {
                        p0 += __shfl_xor_sync(0xffffffffu, p0, off);
                        p1 += __shfl_xor_sync(0xffffffffu, p1, off);
                        p2 += __shfl_xor_sync(0xffffffffu, p2, off);
                        p3 += __shfl_xor_sync(0xffffffffu, p3, off);
                    }
                    if (lane < 12) {
                        int tt = g0 + gg, j = tt + (tt >= i);
                        int v = lane & 3;
                        float wc = (v == 0) ? (p0 + bxv.x) :
                                   (v == 1) ? (p1 + bxv.y) :
                                   (v == 2) ? (p2 + bxv.z) : (p3 + bxv.w);
                        dxr += (xi - xs[j*12 + lane]) * wc;
                    }
                }
                __syncwarp();
            }
            agg[i*64 + lane]      = aggA;
            agg[i*64 + lane + 32] = aggB;
            if (lane < 12) xs[i*12 + lane] = xi + dxr * (1.0f / 11.0f);
        }
        __syncthreads();
        // load WA <- Wh1[l], WB <- Wh2[l]
        {
            float4* q = (float4*)WA;
            const float4* g = (const float4*)Wh1 + l * 2048;
            for (int idx = tid; idx < 2048; idx += TPB) q[idx] = g[idx];
            float4* q2 = (float4*)WB;
            const float4* g2 = (const float4*)Wh2 + l * 1024;
            for (int idx = tid; idx < 1024; idx += TPB) q2[idx] = g2[idx];
        }
        __syncthreads();
        // t1 = silu([h, agg] @ Wh1 + bh1)  -> stored in P
        {
            const int n = w;
            float a0 = __ldg(&bh1[l*64 + lane]);
            float a1 = __ldg(&bh1[l*64 + lane + 32]);
            #pragma unroll
            for (int k = 0; k < 64; k++) {
                float hk = hs[n*64 + k];
                a0 += hk * WA[k*64 + lane];
                a1 += hk * WA[k*64 + lane + 32];
            }
            #pragma unroll
            for (int k = 0; k < 64; k++) {
                float gk = agg[n*64 + k];
                a0 += gk * WA[(64+k)*64 + lane];
                a1 += gk * WA[(64+k)*64 + lane + 32];
            }
            P[n*128 + lane]      = siluf(a0);
            P[n*128 + lane + 32] = siluf(a1);
        }
        __syncthreads();
        // h += t1 @ Wh2 + bh2
        {
            const int n = w;
            float a0 = __ldg(&bh2[l*64 + lane]);
            float a1 = __ldg(&bh2[l*64 + lane + 32]);
            #pragma unroll
            for (int k = 0; k < 64; k++) {
                float tk = P[n*128 + k];
                a0 += tk * WB[k*64 + lane];
                a1 += tk * WB[k*64 + lane + 32];
            }
            hs[n*64 + lane]      += a0;
            hs[n*64 + lane + 32] += a1;
        }
    }
    __syncthreads();
    // ---------- output: mu = x . w_act ; log_probs constant ----------
    if (tid < NAG * 3) {
        int a = tid / 3, d = tid - 3 * a;
        float mu = 0.f;
        #pragma unroll
        for (int v = 0; v < 4; v++) mu += xs[a*12 + d*4 + v] * __ldg(&w_act[v]);
        out[(base + a) * 3 + d] = mu;
        out[NNODE * 3 + (base + a) * 3 + d] =
            -__ldg(&log_std[d]) - 0.91893853320467274178f;  // 0.5*log(2*pi)
    }
}

extern "C" void kernel_launch(void* const* d_in, const int* in_sizes, int n_in,
                              void* d_out, int out_size)
{
    (void)in_sizes; (void)n_in; (void)out_size;
    cudaFuncSetAttribute(egnn_kernel,
                         cudaFuncAttributeMaxDynamicSharedMemorySize, SMEM_BYTES);
    egnn_kernel<<<NENV, TPB, SMEM_BYTES>>>(
        (const float*)d_in[0],  (const float*)d_in[1],
        (const float*)d_in[2],  (const float*)d_in[3],
        (const float*)d_in[4],  (const float*)d_in[5],
        (const float*)d_in[6],  (const float*)d_in[7],
        (const float*)d_in[8],  (const float*)d_in[9],
        (const float*)d_in[10], (const float*)d_in[11],
        (const float*)d_in[12], (const float*)d_in[13],
        (const float*)d_in[14], (const float*)d_in[15],
        (float*)d_out);
}